// round 1
// baseline (speedup 1.0000x reference)
#include <cuda_runtime.h>
#include <math.h>

#define SEQ   2048
#define EMB   1024
#define HID   2048
#define VOCAB 50257
#define WSTRIDE (EMB + HID)   // 3072, row stride of W_i2h

// ---------------- scratch (device globals: allocation-free rule) ----------
__device__ __align__(16) float g_X[SEQ * HID];   // 16 MB: X[t][r] = W_e@e_t + b
__device__ __align__(16) float g_h[2][HID];      // double-buffered hidden state
__device__ unsigned g_bar_count = 0;
__device__ volatile unsigned g_bar_sense = 0;
__device__ int g_tok64 = 0;

// ---------------- token dtype detection ----------------------------------
// jax int64 may arrive as int64 (little-endian: [lo,0] pairs) or int32.
// Reading 2048 int32s is safe under both interpretations (8 KB min buffer).
__global__ void detect_tok_kernel(const int* __restrict__ p) {
    __shared__ int bad;
    if (threadIdx.x == 0) bad = 0;
    __syncthreads();
    int mybad = 0;
    for (int i = threadIdx.x; i < SEQ / 2; i += blockDim.x) {
        int lo = p[2 * i];
        int hi = p[2 * i + 1];
        if (hi != 0 || lo < 0 || lo >= VOCAB) mybad = 1;
    }
    if (mybad) atomicOr(&bad, 1);
    __syncthreads();
    if (threadIdx.x == 0) g_tok64 = bad ? 0 : 1;
}

// ---------------- X = E @ W_e^T + b  (gathered GEMM) ----------------------
#define BM 64
#define BN 64
#define BK 16

__global__ void gemm_x_kernel(const int* __restrict__ toks,
                              const float* __restrict__ emb,
                              const float* __restrict__ Wi2h,
                              const float* __restrict__ bias) {
    __shared__ __align__(16) float As[BK][BM + 4];
    __shared__ __align__(16) float Bs[BK][BN + 4];
    __shared__ int stok[BM];

    const int tid = threadIdx.x;           // 256 threads
    const int t0 = blockIdx.y * BM;        // token (M) tile
    const int r0 = blockIdx.x * BN;        // hidden-row (N) tile
    const int tok64 = g_tok64;

    if (tid < BM) {
        int t = t0 + tid;
        stok[tid] = tok64 ? toks[2 * t] : toks[t];
    }
    __syncthreads();

    float acc[4][4] = {};
    const int tx = tid & 15;   // N
    const int ty = tid >> 4;   // M

    for (int kk = 0; kk < EMB; kk += BK) {
#pragma unroll
        for (int i = 0; i < 4; i++) {
            int idx = tid + i * 256;       // 0..1023
            int m = idx >> 4;
            int k = idx & 15;
            As[k][m] = emb[(size_t)stok[m] * EMB + kk + k];
            Bs[k][m] = Wi2h[(size_t)(r0 + m) * WSTRIDE + kk + k];  // W_e cols [0,1024)
        }
        __syncthreads();
#pragma unroll
        for (int k = 0; k < BK; k++) {
            float4 a4 = *(const float4*)&As[k][ty * 4];
            float4 b4 = *(const float4*)&Bs[k][tx * 4];
            float a[4] = {a4.x, a4.y, a4.z, a4.w};
            float b[4] = {b4.x, b4.y, b4.z, b4.w};
#pragma unroll
            for (int i = 0; i < 4; i++)
#pragma unroll
                for (int j = 0; j < 4; j++) acc[i][j] += a[i] * b[j];
        }
        __syncthreads();
    }

#pragma unroll
    for (int i = 0; i < 4; i++) {
        int t = t0 + ty * 4 + i;
#pragma unroll
        for (int j = 0; j < 4; j++) {
            int r = r0 + tx * 4 + j;
            g_X[(size_t)t * HID + r] = acc[i][j] + bias[r];
        }
    }
}

// ---------------- persistent recurrence kernel ----------------------------
#define NCTA 128
#define ROWS_PER_CTA (HID / NCTA)  // 16
#define RTHREADS 512               // 16 warps
#define SMEM_FLOATS (ROWS_PER_CTA * HID + HID + 64)
#define SMEM_BYTES  (SMEM_FLOATS * 4)

__device__ __forceinline__ void grid_barrier(unsigned* sh_sense) {
    __threadfence();
    __syncthreads();
    if (threadIdx.x == 0) {
        unsigned s = *sh_sense ^ 1u;
        *sh_sense = s;
        unsigned prev = atomicAdd(&g_bar_count, 1u);
        if (prev == gridDim.x - 1) {
            g_bar_count = 0;
            __threadfence();
            g_bar_sense = s;
        } else {
            while (g_bar_sense != s) { }
            __threadfence();
        }
    }
    __syncthreads();
}

__global__ void __launch_bounds__(RTHREADS, 1)
rnn_kernel(const float* __restrict__ Wi2h,
           const float* __restrict__ Wh2o,
           const float* __restrict__ bh2o,
           float* __restrict__ out) {
    extern __shared__ __align__(16) float smem[];
    float* sW   = smem;                          // 16 x 2048
    float* sh   = smem + ROWS_PER_CTA * HID;     // 2048
    float* sred = sh + HID;                      // 64
    __shared__ unsigned sh_sense;

    const int tid = threadIdx.x;
    const int cta = blockIdx.x;
    const int r0  = cta * ROWS_PER_CTA;
    if (tid == 0) sh_sense = 0;

    // Load this CTA's 16 W_h rows into SMEM once (W_h = cols [1024,3072))
    for (int idx = tid; idx < ROWS_PER_CTA * HID; idx += RTHREADS) {
        int r = idx >> 11;       // /2048
        int j = idx & (HID - 1);
        sW[idx] = Wi2h[(size_t)(r0 + r) * WSTRIDE + EMB + j];
    }

    const int w = tid >> 5, l = tid & 31;
    const int grp = w & 3;   // row group: rows r0 + 4*grp .. +3
    const int q   = w >> 2;  // j-slice: [512*q, 512*(q+1))
    const float4* sW4 = (const float4*)sW;
    const float4* sh4 = (const float4*)sh;

    for (int t = 0; t < SEQ; t++) {
        // prefetch this CTA's X[t] slice early (hides L2/HBM latency)
        float xv = 0.f;
        if (tid < ROWS_PER_CTA) xv = g_X[(size_t)t * HID + r0 + tid];

        // stage h_{t-1} into SMEM (h_0 = 0)
        if (t == 0) {
            ((float4*)sh)[tid] = make_float4(0.f, 0.f, 0.f, 0.f);
        } else {
            ((float4*)sh)[tid] = ((const float4*)g_h[(t - 1) & 1])[tid];
        }
        __syncthreads();

        float acc[4] = {0.f, 0.f, 0.f, 0.f};
#pragma unroll
        for (int k = 0; k < 4; k++) {
            int f = (q << 7) + (k << 5) + l;     // float4 index within h
            float4 hv = sh4[f];
#pragma unroll
            for (int rr = 0; rr < 4; rr++) {
                float4 wv = sW4[(size_t)(4 * grp + rr) * (HID / 4) + f];
                acc[rr] += wv.x * hv.x + wv.y * hv.y + wv.z * hv.z + wv.w * hv.w;
            }
        }
#pragma unroll
        for (int rr = 0; rr < 4; rr++) {
            float v = acc[rr];
            v += __shfl_xor_sync(0xffffffffu, v, 16);
            v += __shfl_xor_sync(0xffffffffu, v, 8);
            v += __shfl_xor_sync(0xffffffffu, v, 4);
            v += __shfl_xor_sync(0xffffffffu, v, 2);
            v += __shfl_xor_sync(0xffffffffu, v, 1);
            if (l == 0) sred[w * 4 + rr] = v;
        }
        __syncthreads();

        if (tid < ROWS_PER_CTA) {
            int g = tid >> 2, rr = tid & 3;
            float v = xv;
#pragma unroll
            for (int qq = 0; qq < 4; qq++)
                v += sred[(((qq << 2) | g) << 2) + rr];
            g_h[t & 1][r0 + tid] = v;
        }
        grid_barrier(&sh_sense);   // includes pre/post threadfence
    }

    // readout: out = sigmoid(W_h2o @ h_final + b_h2o); h_final in g_h[1]
    if (cta == 0) {
        const float* hf = g_h[(SEQ - 1) & 1];
        float s = 0.f;
        for (int j = tid; j < HID; j += RTHREADS) s += Wh2o[j] * hf[j];
#pragma unroll
        for (int o = 16; o > 0; o >>= 1) s += __shfl_xor_sync(0xffffffffu, s, o);
        if (l == 0) sred[w] = s;
        __syncthreads();
        if (tid == 0) {
            float tot = 0.f;
#pragma unroll
            for (int i = 0; i < RTHREADS / 32; i++) tot += sred[i];
            tot += bh2o[0];
            out[0] = 1.f / (1.f + expf(-tot));
        }
    }
}

// ---------------- launch ---------------------------------------------------
extern "C" void kernel_launch(void* const* d_in, const int* in_sizes, int n_in,
                              void* d_out, int out_size) {
    const int*   toks = (const int*)d_in[0];
    const float* emb  = (const float*)d_in[1];
    const float* Wi2h = (const float*)d_in[2];
    const float* bi2h = (const float*)d_in[3];
    const float* Wh2o = (const float*)d_in[4];
    const float* bh2o = (const float*)d_in[5];
    float* out = (float*)d_out;

    detect_tok_kernel<<<1, 256>>>(toks);
    gemm_x_kernel<<<dim3(HID / BN, SEQ / BM), 256>>>(toks, emb, Wi2h, bi2h);

    cudaFuncSetAttribute(rnn_kernel, cudaFuncAttributeMaxDynamicSharedMemorySize,
                         SMEM_BYTES);
    rnn_kernel<<<NCTA, RTHREADS, SMEM_BYTES>>>(Wi2h, Wh2o, bh2o, out);
}